// round 3
// baseline (speedup 1.0000x reference)
#include <cuda_runtime.h>
#include <math.h>

#define HH 240
#define WW 320
#define HWP (HH*WW)
#define BB 4
#define CIN 64
#define COUT 24
#define HS 120
#define WS 160
#define NUMK 8

// ---- scratch (static device globals: allowed; no allocation) ----
__device__ float g_oa[BB*COUT*HWP];      // conv output: [b][ch][y][x] (ch 0..15 offsets, 16..23 aff_raw)
__device__ float g_fea[BB*8*HWP];        // upsampled features CHW
__device__ float g_feahwc[BB*HWP*8];     // upsampled features HWC

// ---- f32x2 packed helpers (Blackwell sm_103a) ----
__device__ __forceinline__ unsigned long long pack2(float lo, float hi) {
    unsigned long long r;
    asm("mov.b64 %0, {%1, %2};" : "=l"(r) : "f"(lo), "f"(hi));
    return r;
}
__device__ __forceinline__ void unpack2(float& lo, float& hi, unsigned long long v) {
    asm("mov.b64 {%0, %1}, %2;" : "=f"(lo), "=f"(hi) : "l"(v));
}
__device__ __forceinline__ void ffma2(unsigned long long& acc, unsigned long long a,
                                      unsigned long long b) {
    asm("fma.rn.f32x2 %0, %1, %2, %0;" : "+l"(acc) : "l"(a), "l"(b));
}

// ============================================================================
// bilinear with zeros padding (matches reference _bilinear_zeros)
// ============================================================================
__device__ __forceinline__ float bilin0(const float* __restrict__ img, float x, float y,
                                        int Hi, int Wi) {
    float xf = floorf(x), yf = floorf(y);
    float wx = x - xf, wy = y - yf;
    int x0 = (int)xf, y0 = (int)yf;
    int x1 = x0 + 1, y1 = y0 + 1;

    bool xv0 = (x0 >= 0) && (x0 <= Wi - 1);
    bool xv1 = (x1 >= 0) && (x1 <= Wi - 1);
    bool yv0 = (y0 >= 0) && (y0 <= Hi - 1);
    bool yv1 = (y1 >= 0) && (y1 <= Hi - 1);

    int xc0 = min(max(x0, 0), Wi - 1);
    int xc1 = min(max(x1, 0), Wi - 1);
    int yc0 = min(max(y0, 0), Hi - 1);
    int yc1 = min(max(y1, 0), Hi - 1);

    float v00 = (xv0 && yv0) ? img[yc0 * Wi + xc0] : 0.0f;
    float v10 = (xv1 && yv0) ? img[yc0 * Wi + xc1] : 0.0f;
    float v01 = (xv0 && yv1) ? img[yc1 * Wi + xc0] : 0.0f;
    float v11 = (xv1 && yv1) ? img[yc1 * Wi + xc1] : 0.0f;

    return v00 * ((1.0f - wy) * (1.0f - wx))
         + v10 * ((1.0f - wy) * wx)
         + v01 * (wy * (1.0f - wx))
         + v11 * (wy * wx);
}

// ============================================================================
// Kernel 1: 2x bilinear upsample of tgtimg_fea
// ============================================================================
__global__ void upsample_kernel(const float* __restrict__ tgt) {
    int idx = blockIdx.x * blockDim.x + threadIdx.x;
    if (idx >= BB * HWP) return;
    int b = idx / HWP;
    int P = idx - b * HWP;
    int y = P / WW, x = P - (P / WW) * WW;

    int ty = y >> 1, tx = x >> 1;
    int y0, y1, x0, x1;
    float wy0, wy1, wx0, wx1;
    if (y & 1) { y0 = ty; y1 = min(ty + 1, HS - 1); wy0 = 0.75f; wy1 = 0.25f; }
    else       { y0 = max(ty - 1, 0); y1 = ty;      wy0 = 0.25f; wy1 = 0.75f; }
    if (x & 1) { x0 = tx; x1 = min(tx + 1, WS - 1); wx0 = 0.75f; wx1 = 0.25f; }
    else       { x0 = max(tx - 1, 0); x1 = tx;      wx0 = 0.25f; wx1 = 0.75f; }

    const float* base = tgt + b * 8 * HS * WS;
    #pragma unroll
    for (int c = 0; c < 8; c++) {
        const float* pl = base + c * HS * WS;
        float r0 = wx0 * pl[y0 * WS + x0] + wx1 * pl[y0 * WS + x1];
        float r1 = wx0 * pl[y1 * WS + x0] + wx1 * pl[y1 * WS + x1];
        float v = wy0 * r0 + wy1 * r1;
        g_fea[(b * 8 + c) * HWP + P] = v;
        g_feahwc[(b * HWP + P) * 8 + c] = v;
    }
}

// ============================================================================
// Kernel 2: zero the reference-offset channels (8,9) of offset_full
// ============================================================================
__global__ void zero_kernel(float* __restrict__ out) {
    int idx = blockIdx.x * blockDim.x + threadIdx.x;
    if (idx >= BB * 2 * HWP) return;
    int b = idx / (2 * HWP);
    int r = idx - b * (2 * HWP);
    out[(b * 18 + 8) * HWP + r] = 0.0f;
}

// ============================================================================
// Kernel 3: 3x3 conv 64->24 + bias, FFMA2 (f32x2) inner loop.
// Packing scheme: f32x2 lanes = output-channel PAIR (co, co+1).
//   a-operand: guidance value duplicated {g,g}    (18 dup-packs / ci, ALU pipe)
//   b-operand: {w[co], w[co+1]}                   (two LDGs into pair halves, ~free)
//   accumulators: acc2[3 pairs][4 px]
// FMA-pipe work per ci: 108 FFMA2 (was 216 FFMA) -> 2x throughput, exact fp32.
// ============================================================================
__global__ void conv_kernel(const float* __restrict__ gin, const float* __restrict__ wgt,
                            const float* __restrict__ bias, float* __restrict__ out) {
    __shared__ float sG[6][72];

    int tid = threadIdx.x;
    int pxg = tid & 15;
    int ry  = (tid >> 4) & 3;
    int chg = tid >> 6;
    int bx = blockIdx.x, by = blockIdx.y, b = blockIdx.z;
    int x0 = bx * 64 + pxg * 4;
    int yy = by * 4 + ry;
    int co0 = chg * 6;

    int gy0 = by * 4 - 1;
    int gx0 = bx * 64 - 1;

    unsigned long long acc2[3][4];
    #pragma unroll
    for (int q = 0; q < 3; q++)
        #pragma unroll
        for (int p = 0; p < 4; p++) acc2[q][p] = 0ULL;

    for (int ci = 0; ci < CIN; ci++) {
        __syncthreads();
        const float* gplane = gin + (b * CIN + ci) * HWP;
        #pragma unroll
        for (int it = 0; it < 2; it++) {
            int idx = tid + it * 256;
            if (idx < 6 * 72) {
                int r = idx / 72, c = idx - r * 72;
                float v = 0.0f;
                if (c < 66) {
                    int gy = gy0 + r, gx = gx0 + c;
                    if (gy >= 0 && gy < HH && gx >= 0 && gx < WW)
                        v = __ldg(gplane + gy * WW + gx);
                }
                sG[r][c] = v;
            }
        }
        __syncthreads();

        // duplicate-packed guidance values {g,g}
        unsigned long long gd[3][6];
        #pragma unroll
        for (int rr = 0; rr < 3; rr++)
            #pragma unroll
            for (int cc2 = 0; cc2 < 6; cc2++) {
                float g = sG[ry + rr][pxg * 4 + cc2];
                gd[rr][cc2] = pack2(g, g);
            }

        #pragma unroll
        for (int q = 0; q < 3; q++) {
            const float* wpa = wgt + ((co0 + 2 * q) * CIN + ci) * 9;
            const float* wpb = wpa + CIN * 9;
            unsigned long long w2[9];
            #pragma unroll
            for (int r = 0; r < 9; r++)
                w2[r] = pack2(__ldg(wpa + r), __ldg(wpb + r));
            #pragma unroll
            for (int ky = 0; ky < 3; ky++)
                #pragma unroll
                for (int kx = 0; kx < 3; kx++) {
                    unsigned long long w = w2[ky * 3 + kx];
                    #pragma unroll
                    for (int p = 0; p < 4; p++)
                        ffma2(acc2[q][p], gd[ky][p + kx], w);
                }
        }
    }

    #pragma unroll
    for (int q = 0; q < 3; q++) {
        int coA = co0 + 2 * q;
        int coB = coA + 1;
        float bvA = __ldg(bias + coA);
        float bvB = __ldg(bias + coB);
        float* oaA = g_oa + (b * COUT + coA) * HWP + yy * WW + x0;
        float* oaB = g_oa + (b * COUT + coB) * HWP + yy * WW + x0;
        float* ofA = nullptr;
        float* ofB = nullptr;
        if (coA < 16) {
            int oc = (coA < 8) ? coA : coA + 2;
            ofA = out + (b * 18 + oc) * HWP + yy * WW + x0;
        }
        if (coB < 16) {
            int oc = (coB < 8) ? coB : coB + 2;
            ofB = out + (b * 18 + oc) * HWP + yy * WW + x0;
        }
        #pragma unroll
        for (int p = 0; p < 4; p++) {
            float lo, hi;
            unpack2(lo, hi, acc2[q][p]);
            float vA = lo + bvA;
            float vB = hi + bvB;
            oaA[p] = vA;
            oaB[p] = vB;
            if (ofA) ofA[p] = vA;
            if (ofB) ofB[p] = vB;
        }
    }
}

// ============================================================================
// Kernel 4: fused cos-affinity + confidence + TGASS + softmax.
// (unchanged from R1 — L1-bound at 74us; conv is the bigger lever this round)
// ============================================================================
__global__ void fused_kernel(const float* __restrict__ gtconf,
                             const float* __restrict__ ascp,
                             float* __restrict__ out) {
    int Xg = blockIdx.x * 256 + threadIdx.x;
    int b = Xg / (8 * HWP);
    int X = Xg - b * (8 * HWP);
    int c = X / HWP;
    int P2 = X - c * HWP;
    int P = X >> 3;
    int m = X & 7;
    int i2 = P2 / WW, j2 = P2 - i2 * WW;

    const float* oa_b = g_oa + b * COUT * HWP;
    const float* feac = g_fea + (b * 8 + c) * HWP;
    float fv = g_feahwc[(b * HWP + P) * 8 + m];

    float v[8];
    #pragma unroll
    for (int k = 0; k < 8; k++) {
        float ox = oa_b[(2 * k) * HWP + P2];       // offset[.,k,0]
        float oy = oa_b[(2 * k + 1) * HWP + P2];   // offset[.,k,1]
        float base = (k < 4) ? (float)i2 : (float)j2;  // faithful to ref's repeat bug
        v[k] = fv * bilin0(feac, ox + base, oy + base, HH, WW);
    }

    // ---- 8-lane transpose reduce: lane m ends with sum_m' v_m'[k=m] ----
    int l = threadIdx.x & 31;
    #pragma unroll
    for (int d = 4; d >= 1; d >>= 1) {
        #pragma unroll
        for (int k = 0; k < 8; k++) {
            float o = __shfl_xor_sync(0xffffffffu, v[k], d);
            if (((k ^ l) & d) == 0) v[k] += o;
        }
    }
    float cw = v[m];

    // ---- epilogue: this lane owns k = m for pixel P ----
    int i = P / WW, j = P - i * WW;
    float araw = oa_b[(16 + m) * HWP + P];
    float dy = oa_b[(2 * m) * HWP + P];      // channel 0 = dy
    float dx = oa_b[(2 * m + 1) * HWP + P];  // channel 1 = dx
    const float* gc = gtconf + b * HWP;
    float conf = bilin0(gc, dx + (float)j, dy + (float)i, HH, WW);

    float asc = __ldg(ascp);
    float aff = tanhf(araw * cw) / (asc + 1e-8f);
    aff = aff * conf;

    float s = fabsf(aff);
    s += __shfl_xor_sync(0xffffffffu, s, 1);
    s += __shfl_xor_sync(0xffffffffu, s, 2);
    s += __shfl_xor_sync(0xffffffffu, s, 4);
    float denom = fmaxf(s + 1e-4f, 1.0f);
    float an = aff / denom;

    float t = an;
    t += __shfl_xor_sync(0xffffffffu, t, 1);
    t += __shfl_xor_sync(0xffffffffu, t, 2);
    t += __shfl_xor_sync(0xffffffffu, t, 4);
    float ref = 1.0f - t;

    float mx = an;
    mx = fmaxf(mx, __shfl_xor_sync(0xffffffffu, mx, 1));
    mx = fmaxf(mx, __shfl_xor_sync(0xffffffffu, mx, 2));
    mx = fmaxf(mx, __shfl_xor_sync(0xffffffffu, mx, 4));
    mx = fmaxf(mx, ref);

    float e  = expf(an - mx);
    float er = expf(ref - mx);
    float se = e;
    se += __shfl_xor_sync(0xffffffffu, se, 1);
    se += __shfl_xor_sync(0xffffffffu, se, 2);
    se += __shfl_xor_sync(0xffffffffu, se, 4);
    se += er;
    float inv = 1.0f / se;

    float* outa = out + (size_t)BB * 18 * HWP + (size_t)b * 9 * HWP;
    int oc = (m < 4) ? m : m + 1;
    outa[oc * HWP + P] = e * inv;
    if (m == 0) outa[4 * HWP + P] = er * inv;
}

// ============================================================================
extern "C" void kernel_launch(void* const* d_in, const int* in_sizes, int n_in,
                              void* d_out, int out_size) {
    const float* guidance = (const float*)d_in[0];
    const float* gtconf   = (const float*)d_in[1];
    const float* tgt      = (const float*)d_in[2];
    const float* convw    = (const float*)d_in[3];
    const float* convb    = (const float*)d_in[4];
    const float* asc      = (const float*)d_in[5];
    float* out = (float*)d_out;

    upsample_kernel<<<(BB * HWP + 255) / 256, 256>>>(tgt);
    zero_kernel<<<(BB * 2 * HWP + 255) / 256, 256>>>(out);
    conv_kernel<<<dim3(WW / 64, HH / 4, BB), 256>>>(guidance, convw, convb, out);
    fused_kernel<<<(BB * 8 * HWP) / 256, 256>>>(gtconf, asc, out);
}

// round 4
// speedup vs baseline: 1.1959x; 1.1959x over previous
#include <cuda_runtime.h>
#include <math.h>

#define HH 240
#define WW 320
#define HWP (HH*WW)
#define BB 4
#define CIN 64
#define COUT 24
#define HS 120
#define WS 160
#define NUMK 8

// ---- scratch (static device globals: allowed; no allocation) ----
__device__ float  g_oa[BB*COUT*HWP];     // conv output: [b][ch][y][x] (ch 16..23 = aff_raw used by fused)
__device__ float2 g_off2[BB*NUMK*HWP];   // packed offsets: [b][k][P] = (dy, dx)
__device__ float  g_fea[BB*8*HWP];       // upsampled features CHW
__device__ float  g_feahwc[BB*HWP*8];    // upsampled features HWC

__device__ __forceinline__ float tanh_fast(float x) {
    float y;
    asm("tanh.approx.f32 %0, %1;" : "=f"(y) : "f"(x));
    return y;
}

// ============================================================================
// bilinear with zeros padding (matches reference _bilinear_zeros)
// ============================================================================
__device__ __forceinline__ float bilin0(const float* __restrict__ img, float x, float y,
                                        int Hi, int Wi) {
    float xf = floorf(x), yf = floorf(y);
    float wx = x - xf, wy = y - yf;
    int x0 = (int)xf, y0 = (int)yf;
    int x1 = x0 + 1, y1 = y0 + 1;

    bool xv0 = (x0 >= 0) && (x0 <= Wi - 1);
    bool xv1 = (x1 >= 0) && (x1 <= Wi - 1);
    bool yv0 = (y0 >= 0) && (y0 <= Hi - 1);
    bool yv1 = (y1 >= 0) && (y1 <= Hi - 1);

    int xc0 = min(max(x0, 0), Wi - 1);
    int xc1 = min(max(x1, 0), Wi - 1);
    int yc0 = min(max(y0, 0), Hi - 1);
    int yc1 = min(max(y1, 0), Hi - 1);

    float v00 = (xv0 && yv0) ? img[yc0 * Wi + xc0] : 0.0f;
    float v10 = (xv1 && yv0) ? img[yc0 * Wi + xc1] : 0.0f;
    float v01 = (xv0 && yv1) ? img[yc1 * Wi + xc0] : 0.0f;
    float v11 = (xv1 && yv1) ? img[yc1 * Wi + xc1] : 0.0f;

    return v00 * ((1.0f - wy) * (1.0f - wx))
         + v10 * ((1.0f - wy) * wx)
         + v01 * (wy * (1.0f - wx))
         + v11 * (wy * wx);
}

// ============================================================================
// Kernel 1: 2x bilinear upsample of tgtimg_fea
// ============================================================================
__global__ void upsample_kernel(const float* __restrict__ tgt) {
    int idx = blockIdx.x * blockDim.x + threadIdx.x;
    if (idx >= BB * HWP) return;
    int b = idx / HWP;
    int P = idx - b * HWP;
    int y = P / WW, x = P - (P / WW) * WW;

    int ty = y >> 1, tx = x >> 1;
    int y0, y1, x0, x1;
    float wy0, wy1, wx0, wx1;
    if (y & 1) { y0 = ty; y1 = min(ty + 1, HS - 1); wy0 = 0.75f; wy1 = 0.25f; }
    else       { y0 = max(ty - 1, 0); y1 = ty;      wy0 = 0.25f; wy1 = 0.75f; }
    if (x & 1) { x0 = tx; x1 = min(tx + 1, WS - 1); wx0 = 0.75f; wx1 = 0.25f; }
    else       { x0 = max(tx - 1, 0); x1 = tx;      wx0 = 0.25f; wx1 = 0.75f; }

    const float* base = tgt + b * 8 * HS * WS;
    #pragma unroll
    for (int c = 0; c < 8; c++) {
        const float* pl = base + c * HS * WS;
        float r0 = wx0 * pl[y0 * WS + x0] + wx1 * pl[y0 * WS + x1];
        float r1 = wx0 * pl[y1 * WS + x0] + wx1 * pl[y1 * WS + x1];
        float v = wy0 * r0 + wy1 * r1;
        g_fea[(b * 8 + c) * HWP + P] = v;
        g_feahwc[(b * HWP + P) * 8 + c] = v;
    }
}

// ============================================================================
// Kernel 2: 3x3 conv 64->24 + bias (scalar FFMA).
// Block = 256 threads = 16 pixel-groups (x4 px) x 4 rows x 4 channel-groups (x6 co).
// Stages 4 input-channel planes per __syncthreads pair (32 barriers instead of
// 128; fill is 7 front-batched LDGs -> latency hidden by MLP).
// Also: zeros out-channels 8/9 (reference offset) and writes packed offsets
// into g_off2 for the fused kernel.
// ============================================================================
__global__ void conv_kernel(const float* __restrict__ gin, const float* __restrict__ wgt,
                            const float* __restrict__ bias, float* __restrict__ out) {
    __shared__ float sG[4][6][72];

    int tid = threadIdx.x;
    int pxg = tid & 15;
    int ry  = (tid >> 4) & 3;
    int chg = tid >> 6;
    int bx = blockIdx.x, by = blockIdx.y, b = blockIdx.z;
    int x0 = bx * 64 + pxg * 4;
    int yy = by * 4 + ry;
    int co0 = chg * 6;

    int gy0 = by * 4 - 1;
    int gx0 = bx * 64 - 1;

    float acc[6][4];
    #pragma unroll
    for (int cc = 0; cc < 6; cc++)
        #pragma unroll
        for (int p = 0; p < 4; p++) acc[cc][p] = 0.0f;

    const float* gbase = gin + (size_t)b * CIN * HWP;

    for (int cib = 0; cib < CIN / 4; cib++) {
        __syncthreads();
        #pragma unroll
        for (int it = 0; it < 7; it++) {
            int idx = tid + it * 256;
            if (idx < 4 * 6 * 72) {
                int ciq = idx / 432;
                int rem = idx - ciq * 432;
                int r = rem / 72, c = rem - r * 72;
                float v = 0.0f;
                if (c < 66) {
                    int gy = gy0 + r, gx = gx0 + c;
                    if (gy >= 0 && gy < HH && gx >= 0 && gx < WW)
                        v = __ldg(gbase + (size_t)(cib * 4 + ciq) * HWP + gy * WW + gx);
                }
                sG[ciq][r][c] = v;
            }
        }
        __syncthreads();

        #pragma unroll
        for (int ciq = 0; ciq < 4; ciq++) {
            int ci = cib * 4 + ciq;

            float gr[3][6];
            #pragma unroll
            for (int rr = 0; rr < 3; rr++)
                #pragma unroll
                for (int cc2 = 0; cc2 < 6; cc2++)
                    gr[rr][cc2] = sG[ciq][ry + rr][pxg * 4 + cc2];

            #pragma unroll
            for (int cc = 0; cc < 6; cc++) {
                const float* wp = wgt + ((co0 + cc) * CIN + ci) * 9;
                float wr[9];
                #pragma unroll
                for (int r = 0; r < 9; r++) wr[r] = __ldg(wp + r);
                #pragma unroll
                for (int ky = 0; ky < 3; ky++)
                    #pragma unroll
                    for (int kx = 0; kx < 3; kx++)
                        #pragma unroll
                        for (int p = 0; p < 4; p++)
                            acc[cc][p] = fmaf(gr[ky][p + kx], wr[ky * 3 + kx], acc[cc][p]);
            }
        }
    }

    // ---- epilogue: bias, stores (g_oa, out offsets, packed g_off2, zero ch 8/9) ----
    float v[6][4];
    #pragma unroll
    for (int cc = 0; cc < 6; cc++) {
        int co = co0 + cc;
        float bv = __ldg(bias + co);
        float* oa = g_oa + ((size_t)b * COUT + co) * HWP + yy * WW + x0;
        float* ofull = nullptr;
        if (co < 16) {
            int oc = (co < 8) ? co : co + 2;
            ofull = out + ((size_t)b * 18 + oc) * HWP + yy * WW + x0;
        }
        #pragma unroll
        for (int p = 0; p < 4; p++) {
            v[cc][p] = acc[cc][p] + bv;
            oa[p] = v[cc][p];
            if (ofull) ofull[p] = v[cc][p];
        }
    }

    // packed offset pairs (co pairs within this thread's 6 channels)
    #pragma unroll
    for (int q = 0; q < 3; q++) {
        int co = co0 + 2 * q;
        if (co < 16) {
            float2* op = g_off2 + ((size_t)b * NUMK + (co >> 1)) * HWP + yy * WW + x0;
            #pragma unroll
            for (int p = 0; p < 4; p++)
                op[p] = make_float2(v[2 * q][p], v[2 * q + 1][p]);
        }
    }

    // zero reference-offset channels 8,9 of offset_full
    if (chg == 0) {
        float* z8 = out + ((size_t)b * 18 + 8) * HWP + yy * WW + x0;
        float* z9 = out + ((size_t)b * 18 + 9) * HWP + yy * WW + x0;
        #pragma unroll
        for (int p = 0; p < 4; p++) { z8[p] = 0.0f; z9[p] = 0.0f; }
    }
}

// ============================================================================
// Kernel 3: fused cos-affinity + confidence + TGASS + softmax.
// Offsets read as packed float2 (8 coalesced LDG.64 instead of 16 strided
// LDG.32); fast tanh/exp/div (precision budget: 1e-3 vs current 5e-7).
// ============================================================================
__global__ void fused_kernel(const float* __restrict__ gtconf,
                             const float* __restrict__ ascp,
                             float* __restrict__ out) {
    int Xg = blockIdx.x * 256 + threadIdx.x;
    int b = Xg / (8 * HWP);
    int X = Xg - b * (8 * HWP);
    int c = X / HWP;
    int P2 = X - c * HWP;
    int P = X >> 3;
    int m = X & 7;
    int i2 = P2 / WW, j2 = P2 - i2 * WW;

    const float2* off_b = g_off2 + (size_t)b * NUMK * HWP;
    const float*  oa_b  = g_oa + (size_t)b * COUT * HWP;
    const float*  feac  = g_fea + ((size_t)b * 8 + c) * HWP;
    float fv = g_feahwc[((size_t)b * HWP + P) * 8 + m];

    float v[8];
    #pragma unroll
    for (int k = 0; k < 8; k++) {
        float2 o = off_b[(size_t)k * HWP + P2];        // (dy, dx) = (offset ch0, ch1)
        float base = (k < 4) ? (float)i2 : (float)j2;  // faithful to ref's repeat bug
        v[k] = fv * bilin0(feac, o.x + base, o.y + base, HH, WW);
    }

    // ---- 8-lane transpose reduce: lane m ends with sum_m' v_m'[k=m] ----
    int l = threadIdx.x & 31;
    #pragma unroll
    for (int d = 4; d >= 1; d >>= 1) {
        #pragma unroll
        for (int k = 0; k < 8; k++) {
            float o = __shfl_xor_sync(0xffffffffu, v[k], d);
            if (((k ^ l) & d) == 0) v[k] += o;
        }
    }
    float cw = v[m];

    // ---- epilogue: this lane owns k = m for pixel P ----
    int i = P / WW, j = P - i * WW;
    float araw = oa_b[(size_t)(16 + m) * HWP + P];
    float2 od = off_b[(size_t)m * HWP + P];            // (dy, dx)
    const float* gc = gtconf + (size_t)b * HWP;
    float conf = bilin0(gc, od.y + (float)j, od.x + (float)i, HH, WW);

    float asc = __ldg(ascp);
    float aff = __fdividef(tanh_fast(araw * cw), asc + 1e-8f);
    aff = aff * conf;

    float s = fabsf(aff);
    s += __shfl_xor_sync(0xffffffffu, s, 1);
    s += __shfl_xor_sync(0xffffffffu, s, 2);
    s += __shfl_xor_sync(0xffffffffu, s, 4);
    float denom = fmaxf(s + 1e-4f, 1.0f);
    float an = __fdividef(aff, denom);

    float t = an;
    t += __shfl_xor_sync(0xffffffffu, t, 1);
    t += __shfl_xor_sync(0xffffffffu, t, 2);
    t += __shfl_xor_sync(0xffffffffu, t, 4);
    float ref = 1.0f - t;

    float mx = an;
    mx = fmaxf(mx, __shfl_xor_sync(0xffffffffu, mx, 1));
    mx = fmaxf(mx, __shfl_xor_sync(0xffffffffu, mx, 2));
    mx = fmaxf(mx, __shfl_xor_sync(0xffffffffu, mx, 4));
    mx = fmaxf(mx, ref);

    float e  = __expf(an - mx);
    float er = __expf(ref - mx);
    float se = e;
    se += __shfl_xor_sync(0xffffffffu, se, 1);
    se += __shfl_xor_sync(0xffffffffu, se, 2);
    se += __shfl_xor_sync(0xffffffffu, se, 4);
    se += er;
    float inv = __fdividef(1.0f, se);

    float* outa = out + (size_t)BB * 18 * HWP + (size_t)b * 9 * HWP;
    int oc = (m < 4) ? m : m + 1;
    outa[(size_t)oc * HWP + P] = e * inv;
    if (m == 0) outa[(size_t)4 * HWP + P] = er * inv;
}

// ============================================================================
extern "C" void kernel_launch(void* const* d_in, const int* in_sizes, int n_in,
                              void* d_out, int out_size) {
    const float* guidance = (const float*)d_in[0];
    const float* gtconf   = (const float*)d_in[1];
    const float* tgt      = (const float*)d_in[2];
    const float* convw    = (const float*)d_in[3];
    const float* convb    = (const float*)d_in[4];
    const float* asc      = (const float*)d_in[5];
    float* out = (float*)d_out;

    upsample_kernel<<<(BB * HWP + 255) / 256, 256>>>(tgt);
    conv_kernel<<<dim3(WW / 64, HH / 4, BB), 256>>>(guidance, convw, convb, out);
    fused_kernel<<<(BB * 8 * HWP) / 256, 256>>>(gtconf, asc, out);
}